// round 1
// baseline (speedup 1.0000x reference)
#include <cuda_runtime.h>
#include <math.h>

#define NN 50000
#define NE 800000
#define IN_CH 128
#define OUT_CH 64
#define HEADS 8

// ---- device scratch (no allocation allowed) ----
__device__ float4 g_h[NN * 16];       // h = x@W, [NN,64] as float4
__device__ float  g_s1[NN];           // dot(h[n], a[:64])
__device__ float  g_s2[NN];           // dot(h[n], a[64:])
__device__ float  g_logit[NE];        // logits, then exp values
__device__ float4 g_accum[NN * 16];   // scatter-add accumulator
__device__ float  g_max;
__device__ float  g_sum;

__device__ __forceinline__ void atomicMaxFloat(float* addr, float value) {
    if (value >= 0.f) atomicMax((int*)addr, __float_as_int(value));
    else              atomicMin((unsigned int*)addr, __float_as_uint(value));
}

// ---------------- K0: init ----------------
__global__ void k_init() {
    int idx = blockIdx.x * blockDim.x + threadIdx.x;
    float4 z = make_float4(0.f, 0.f, 0.f, 0.f);
    for (int i = idx; i < NN * 16; i += gridDim.x * blockDim.x) g_accum[i] = z;
    if (idx == 0) { g_max = __int_as_float(0xFF800000); g_sum = 0.f; }
}

// ---------------- K1: h = x @ W, plus per-node attention scores ----------------
// grid-stride over 32-node tiles; 256 threads; thread = (node_local 0..31, cgroup 0..7)
// each thread computes 8 output columns for 1 node.
__global__ void k_gemm(const float* __restrict__ x,
                       const float* __restrict__ W,
                       const float* __restrict__ attn) {
    extern __shared__ float sh[];
    float* Ws = sh;                 // 128*64 = 8192 floats
    float* xs = sh + 8192;          // 32*128 = 4096 floats
    float* aw = sh + 8192 + 4096;   // 128 floats
    int t = threadIdx.x;
    for (int i = t; i < 8192; i += 256) Ws[i] = W[i];
    if (t < 128) aw[t] = attn[t];

    int nl = t >> 3;    // node within tile
    int cg = t & 7;     // column group (8 cols each)

    const float4* x4  = (const float4*)x;
    const float4* ws4 = (const float4*)Ws;
    float4* xs4 = (float4*)xs;

    for (int tile = blockIdx.x * 32; tile < NN; tile += gridDim.x * 32) {
        __syncthreads();
        for (int i = t; i < 32 * 32; i += 256) {
            int node = tile + (i >> 5);
            float4 v = make_float4(0.f, 0.f, 0.f, 0.f);
            if (node < NN) v = x4[node * 32 + (i & 31)];
            xs4[i] = v;
        }
        __syncthreads();

        float acc[8];
        #pragma unroll
        for (int j = 0; j < 8; j++) acc[j] = 0.f;

        const float4* xrow = (const float4*)(xs + nl * 128);
        #pragma unroll 4
        for (int k4 = 0; k4 < 32; k4++) {
            float4 xv = xrow[k4];
            #pragma unroll
            for (int s = 0; s < 4; s++) {
                int k = k4 * 4 + s;
                float xvs = (s == 0) ? xv.x : (s == 1) ? xv.y : (s == 2) ? xv.z : xv.w;
                float4 w0 = ws4[k * 16 + cg * 2];
                float4 w1 = ws4[k * 16 + cg * 2 + 1];
                acc[0] += xvs * w0.x; acc[1] += xvs * w0.y;
                acc[2] += xvs * w0.z; acc[3] += xvs * w0.w;
                acc[4] += xvs * w1.x; acc[5] += xvs * w1.y;
                acc[6] += xvs * w1.z; acc[7] += xvs * w1.w;
            }
        }

        int n = tile + nl;
        if (n < NN) {
            g_h[n * 16 + cg * 2]     = make_float4(acc[0], acc[1], acc[2], acc[3]);
            g_h[n * 16 + cg * 2 + 1] = make_float4(acc[4], acc[5], acc[6], acc[7]);
            int cb = cg * 8;
            float p1 = 0.f, p2 = 0.f;
            #pragma unroll
            for (int j = 0; j < 8; j++) {
                p1 += acc[j] * aw[cb + j];
                p2 += acc[j] * aw[64 + cb + j];
            }
            // reduce across the 8 cgroup lanes of this node (consecutive lanes)
            #pragma unroll
            for (int o = 4; o > 0; o >>= 1) {
                p1 += __shfl_down_sync(0xffffffffu, p1, o, 8);
                p2 += __shfl_down_sync(0xffffffffu, p2, o, 8);
            }
            if (cg == 0) { g_s1[n] = p1; g_s2[n] = p2; }
        }
    }
}

// ---------------- K2: per-edge logits + global max ----------------
__global__ void k_logits(const int* __restrict__ eidx) {
    int e = blockIdx.x * blockDim.x + threadIdx.x;
    float v = -3.4e38f;
    if (e < NE) {
        int i = eidx[e];
        int j = eidx[NE + e];
        float l = g_s1[i] + g_s2[j];
        l = (l > 0.f) ? l : 0.2f * l;    // leaky_relu slope 0.2
        g_logit[e] = l;
        v = l;
    }
    #pragma unroll
    for (int o = 16; o > 0; o >>= 1) v = fmaxf(v, __shfl_down_sync(0xffffffffu, v, o));
    __shared__ float wmax[8];
    int w = threadIdx.x >> 5, lane = threadIdx.x & 31;
    if (lane == 0) wmax[w] = v;
    __syncthreads();
    if (w == 0) {
        v = (lane < 8) ? wmax[lane] : -3.4e38f;
        #pragma unroll
        for (int o = 4; o > 0; o >>= 1) v = fmaxf(v, __shfl_down_sync(0xffffffffu, v, o));
        if (lane == 0) atomicMaxFloat(&g_max, v);
    }
}

// ---------------- K3: exp(logit - max), global sum ----------------
__global__ void k_expsum() {
    int e = blockIdx.x * blockDim.x + threadIdx.x;
    float gmax = g_max;
    float v = 0.f;
    if (e < NE) {
        float ex = expf(g_logit[e] - gmax);
        g_logit[e] = ex;
        v = ex;
    }
    #pragma unroll
    for (int o = 16; o > 0; o >>= 1) v += __shfl_down_sync(0xffffffffu, v, o);
    __shared__ float wsum[8];
    int w = threadIdx.x >> 5, lane = threadIdx.x & 31;
    if (lane == 0) wsum[w] = v;
    __syncthreads();
    if (w == 0) {
        v = (lane < 8) ? wsum[lane] : 0.f;
        #pragma unroll
        for (int o = 4; o > 0; o >>= 1) v += __shfl_down_sync(0xffffffffu, v, o);
        if (lane == 0) atomicAdd(&g_sum, v);
    }
}

// ---------------- K4: msg = h[ej]*alpha, scatter-add into accum[ei] ----------------
// 2 edges per warp; 16 lanes per edge; one red.global.add.v4.f32 per lane.
__global__ void k_scatter(const int* __restrict__ eidx) {
    int gt = blockIdx.x * blockDim.x + threadIdx.x;
    int lane = gt & 31;
    int warp = gt >> 5;
    int e = warp * 2 + (lane >> 4);
    if (e >= NE) return;
    int l16 = lane & 15;
    float inv = 1.0f / g_sum;
    float alpha = g_logit[e] * inv;   // g_logit holds exp values now
    int i = eidx[e];
    int j = eidx[NE + e];
    float4 hv = g_h[j * 16 + l16];
    float mx = hv.x * alpha, my = hv.y * alpha, mz = hv.z * alpha, mw = hv.w * alpha;
    float* dst = (float*)g_accum + (size_t)i * 64 + l16 * 4;
    asm volatile("red.global.add.v4.f32 [%0], {%1, %2, %3, %4};"
                 :: "l"(dst), "f"(mx), "f"(my), "f"(mz), "f"(mw) : "memory");
}

// ---------------- K5: tile head-0 result into 8 heads ----------------
__global__ void k_expand(float* __restrict__ out) {
    int idx = blockIdx.x * blockDim.x + threadIdx.x;
    if (idx >= NN * 16) return;
    int n  = idx >> 4;
    int c4 = idx & 15;
    float4 v = g_accum[idx];
    float4* o = (float4*)out + (size_t)n * 128;   // 512 floats/row = 128 float4
    #pragma unroll
    for (int hh = 0; hh < 8; hh++) o[hh * 16 + c4] = v;
}

extern "C" void kernel_launch(void* const* d_in, const int* in_sizes, int n_in,
                              void* d_out, int out_size) {
    const float* x    = (const float*)d_in[0];
    const int*   eidx = (const int*)d_in[1];
    const float* W    = (const float*)d_in[2];
    const float* attn = (const float*)d_in[3];
    float* out = (float*)d_out;

    const int smem = (8192 + 4096 + 128) * 4;   // 49664 B > 48KB default
    cudaFuncSetAttribute(k_gemm, cudaFuncAttributeMaxDynamicSharedMemorySize, smem);

    k_init<<<2048, 256>>>();
    k_gemm<<<592, 256, smem>>>(x, W, attn);
    k_logits<<<(NE + 255) / 256, 256>>>(eidx);
    k_expsum<<<(NE + 255) / 256, 256>>>();
    // NE/2 warps -> NE/2*32 threads
    k_scatter<<<(NE / 2 * 32 + 255) / 256, 256>>>(eidx);
    k_expand<<<(NN * 16 + 255) / 256, 256>>>(out);
}

// round 2
// speedup vs baseline: 1.4429x; 1.4429x over previous
#include <cuda_runtime.h>
#include <math.h>

#define NN 50000
#define NE 800000

// ---- device scratch ----
__device__ float4 g_h[NN * 16];       // h = x@W, [NN,64] as float4
__device__ float  g_s1[NN];           // dot(h[n], a[:64])
__device__ float  g_s2[NN];           // dot(h[n], a[64:])
__device__ float4 g_accum[NN * 16];   // unnormalized scatter-add accumulator
__device__ float  g_sum;              // sum of exp(logits)

// ---------------- K1: h = x@W + per-node scores; also zeroes accum ----------------
// 391 blocks x 256 threads; tile = 128 nodes/block; thread = (nl 0..31, cg 0..7),
// 4 nodes x 8 cols per thread (32 accumulators) -> W smem loads amortized 4x.
__global__ void k_gemm(const float* __restrict__ x,
                       const float* __restrict__ W,
                       const float* __restrict__ attn) {
    extern __shared__ float sh[];
    float* Ws = sh;                    // 128*64 = 8192 floats
    float* xs = sh + 8192;             // 128 nodes * 132 (padded) = 16896 floats
    float* aw = sh + 8192 + 16896;     // 128 floats
    const int t = threadIdx.x;
    const int gt = blockIdx.x * 256 + t;

    // prologue: zero accumulator + sum (replaces separate init kernel)
    float4 z = make_float4(0.f, 0.f, 0.f, 0.f);
    for (int i = gt; i < NN * 16; i += gridDim.x * 256) g_accum[i] = z;
    if (gt == 0) g_sum = 0.f;

    for (int i = t; i < 8192; i += 256) Ws[i] = W[i];
    if (t < 128) aw[t] = attn[t];

    const int nl = t >> 3;   // node slot 0..31
    const int cg = t & 7;    // column group (8 cols)
    const int tile = blockIdx.x * 128;

    const float4* x4 = (const float4*)x;
    float4* xs4 = (float4*)xs;

    // stage x tile: 128 nodes * 32 float4, row stride 33 float4 (pad kills bank conflicts)
    for (int i = t; i < 4096; i += 256) {
        int nloc = i >> 5, kq = i & 31;
        int node = tile + nloc;
        float4 v = z;
        if (node < NN) v = x4[(size_t)node * 32 + kq];
        xs4[nloc * 33 + kq] = v;
    }
    __syncthreads();

    float acc[32];
    #pragma unroll
    for (int q = 0; q < 32; q++) acc[q] = 0.f;

    const float4* ws4 = (const float4*)Ws;
    #pragma unroll 2
    for (int k4 = 0; k4 < 32; k4++) {
        float4 xv[4];
        #pragma unroll
        for (int m = 0; m < 4; m++) xv[m] = xs4[(nl + 32 * m) * 33 + k4];
        #pragma unroll
        for (int s = 0; s < 4; s++) {
            int k = k4 * 4 + s;
            float4 w0 = ws4[k * 16 + cg * 2];
            float4 w1 = ws4[k * 16 + cg * 2 + 1];
            #pragma unroll
            for (int m = 0; m < 4; m++) {
                float xvs = (s == 0) ? xv[m].x : (s == 1) ? xv[m].y
                          : (s == 2) ? xv[m].z : xv[m].w;
                acc[m * 8 + 0] += xvs * w0.x; acc[m * 8 + 1] += xvs * w0.y;
                acc[m * 8 + 2] += xvs * w0.z; acc[m * 8 + 3] += xvs * w0.w;
                acc[m * 8 + 4] += xvs * w1.x; acc[m * 8 + 5] += xvs * w1.y;
                acc[m * 8 + 6] += xvs * w1.z; acc[m * 8 + 7] += xvs * w1.w;
            }
        }
    }

    #pragma unroll
    for (int m = 0; m < 4; m++) {
        int n = tile + nl + 32 * m;
        float p1 = 0.f, p2 = 0.f;
        #pragma unroll
        for (int q = 0; q < 8; q++) {
            p1 += acc[m * 8 + q] * aw[cg * 8 + q];
            p2 += acc[m * 8 + q] * aw[64 + cg * 8 + q];
        }
        #pragma unroll
        for (int o = 4; o > 0; o >>= 1) {
            p1 += __shfl_down_sync(0xffffffffu, p1, o, 8);
            p2 += __shfl_down_sync(0xffffffffu, p2, o, 8);
        }
        if (n < NN) {
            g_h[n * 16 + cg * 2]     = make_float4(acc[m*8+0], acc[m*8+1], acc[m*8+2], acc[m*8+3]);
            g_h[n * 16 + cg * 2 + 1] = make_float4(acc[m*8+4], acc[m*8+5], acc[m*8+6], acc[m*8+7]);
            if (cg == 0) { g_s1[n] = p1; g_s2[n] = p2; }
        }
    }
}

// ---------------- K2: fused edge pass ----------------
// exp(leaky(s1[i]+s2[j])) once per edge (lane l16==0, shfl-broadcast),
// unnormalized scatter via red.global.add.v4.f32, global sum via block reduction.
__global__ void k_edge(const int* __restrict__ eidx) {
    const int t = blockIdx.x * blockDim.x + threadIdx.x;
    const int lane = threadIdx.x & 31;
    const int warp = t >> 5;
    const int nwarps = (gridDim.x * blockDim.x) >> 5;
    const int half = lane >> 4;
    const int l16 = lane & 15;

    float lsum = 0.f;
    for (int e0 = warp * 2; e0 < NE; e0 += nwarps * 2) {
        int e = e0 + half;                      // NE is even -> always valid
        int i = __ldg(eidx + e);
        int j = __ldg(eidx + NE + e);
        float expv = 0.f;
        if (l16 == 0) {
            float l = g_s1[i] + g_s2[j];
            l = (l > 0.f) ? l : 0.2f * l;       // leaky_relu 0.2
            expv = __expf(l);
            lsum += expv;
        }
        expv = __shfl_sync(0xffffffffu, expv, lane & 16);  // broadcast within 16-lane group
        float4 hv = g_h[(size_t)j * 16 + l16];
        float* dst = (float*)g_accum + (size_t)i * 64 + l16 * 4;
        asm volatile("red.global.add.v4.f32 [%0], {%1, %2, %3, %4};"
                     :: "l"(dst), "f"(hv.x * expv), "f"(hv.y * expv),
                        "f"(hv.z * expv), "f"(hv.w * expv) : "memory");
    }

    // block-reduce lsum -> one atomic per block
    #pragma unroll
    for (int o = 16; o > 0; o >>= 1) lsum += __shfl_down_sync(0xffffffffu, lsum, o);
    __shared__ float wr[8];
    int w = threadIdx.x >> 5;
    if (lane == 0) wr[w] = lsum;
    __syncthreads();
    if (w == 0) {
        float v = (lane < 8) ? wr[lane] : 0.f;
        #pragma unroll
        for (int o = 4; o > 0; o >>= 1) v += __shfl_down_sync(0xffffffffu, v, o);
        if (lane == 0) atomicAdd(&g_sum, v);
    }
}

// ---------------- K3: normalize + tile into 8 heads ----------------
__global__ void k_expand(float* __restrict__ out) {
    int idx = blockIdx.x * blockDim.x + threadIdx.x;
    if (idx >= NN * 16) return;
    float inv = 1.0f / g_sum;
    int n = idx >> 4;
    int c4 = idx & 15;
    float4 v = g_accum[idx];
    v.x *= inv; v.y *= inv; v.z *= inv; v.w *= inv;
    float4* o = (float4*)out + (size_t)n * 128;   // 512 floats/row
    #pragma unroll
    for (int hh = 0; hh < 8; hh++) o[hh * 16 + c4] = v;
}

extern "C" void kernel_launch(void* const* d_in, const int* in_sizes, int n_in,
                              void* d_out, int out_size) {
    const float* x    = (const float*)d_in[0];
    const int*   eidx = (const int*)d_in[1];
    const float* W    = (const float*)d_in[2];
    const float* attn = (const float*)d_in[3];
    float* out = (float*)d_out;

    const int smem = (8192 + 16896 + 128) * 4;   // 100,864 B
    cudaFuncSetAttribute(k_gemm, cudaFuncAttributeMaxDynamicSharedMemorySize, smem);

    k_gemm<<<391, 256, smem>>>(x, W, attn);      // 391*128 = 50048 >= NN
    k_edge<<<2048, 256>>>(eidx);
    k_expand<<<(NN * 16 + 255) / 256, 256>>>(out);
}

// round 3
// speedup vs baseline: 1.8543x; 1.2851x over previous
#include <cuda_runtime.h>
#include <math.h>

#define NN 50000
#define NE 800000
#define NPB 338          // nodes per gemm block; 148*338 = 50024 >= NN

// ---- device scratch ----
__device__ float4 g_h[NN * 16];       // h = x@W, [NN,64] as float4
__device__ float  g_s1[NN];           // dot(h[n], a[:64])
__device__ float  g_s2[NN];           // dot(h[n], a[64:])
__device__ float4 g_accum[NN * 16];   // unnormalized scatter-add accumulator
__device__ float  g_sum;              // sum of exp(logits)

// ---------------- K0: zero accumulator + sum ----------------
__global__ void k_zero() {
    int idx = blockIdx.x * blockDim.x + threadIdx.x;
    if (idx < NN * 16) g_accum[idx] = make_float4(0.f, 0.f, 0.f, 0.f);
    if (idx == 0) g_sum = 0.f;
}

// ---------------- K1: h = x@W + per-node scores ----------------
// 148 blocks x 256 threads, 338 nodes/block, 2 nodes/thread, full 64-col output
// row per node held in f32x2 packed accumulators. W in smem (broadcast LDS.128).
__global__ void __launch_bounds__(256, 1)
k_gemm(const float* __restrict__ x,
       const float* __restrict__ W,
       const float* __restrict__ attn) {
    __shared__ ulonglong2 Ws2[128 * 16];   // W[k][0:64] as 16B chunks (2 f32-pairs each)
    __shared__ float aws[128];
    const int t = threadIdx.x;

    {
        const float4* W4 = (const float4*)W;
        float4* Ws4 = (float4*)Ws2;
        for (int i = t; i < 2048; i += 256) Ws4[i] = W4[i];
        if (t < 128) aws[t] = attn[t];
    }
    __syncthreads();

    const int base = blockIdx.x * NPB;
    const int n0 = base + 2 * t;
    if (2 * t >= NPB || n0 >= NN) return;
    const int n1 = n0 + 1;
    const size_t r0 = (size_t)n0;
    const size_t r1 = (size_t)((n1 < NN) ? n1 : n0);   // clamp to avoid OOB read

    unsigned long long accA[32], accB[32];
    #pragma unroll
    for (int c = 0; c < 32; c++) { accA[c] = 0ull; accB[c] = 0ull; }

    const float4* x4 = (const float4*)x;

    #pragma unroll 1
    for (int k4 = 0; k4 < 32; k4++) {
        float4 xa = x4[r0 * 32 + k4];
        float4 xb = x4[r1 * 32 + k4];
        #pragma unroll
        for (int s = 0; s < 4; s++) {
            float fa = (s == 0) ? xa.x : (s == 1) ? xa.y : (s == 2) ? xa.z : xa.w;
            float fb = (s == 0) ? xb.x : (s == 1) ? xb.y : (s == 2) ? xb.z : xb.w;
            unsigned long long pa, pb;
            asm("mov.b64 %0, {%1, %1};" : "=l"(pa) : "f"(fa));
            asm("mov.b64 %0, {%1, %1};" : "=l"(pb) : "f"(fb));
            const ulonglong2* wk = Ws2 + (k4 * 4 + s) * 16;
            #pragma unroll
            for (int c = 0; c < 16; c++) {
                ulonglong2 wv = wk[c];
                asm("fma.rn.f32x2 %0, %1, %2, %0;" : "+l"(accA[2*c])   : "l"(pa), "l"(wv.x));
                asm("fma.rn.f32x2 %0, %1, %2, %0;" : "+l"(accA[2*c+1]) : "l"(pa), "l"(wv.y));
                asm("fma.rn.f32x2 %0, %1, %2, %0;" : "+l"(accB[2*c])   : "l"(pb), "l"(wv.x));
                asm("fma.rn.f32x2 %0, %1, %2, %0;" : "+l"(accB[2*c+1]) : "l"(pb), "l"(wv.y));
            }
        }
    }

    // epilogue: store h rows + per-node attention scores (all in-thread)
    {
        float s1 = 0.f, s2 = 0.f;
        #pragma unroll
        for (int q = 0; q < 16; q++) {
            float4 v;
            asm("mov.b64 {%0, %1}, %2;" : "=f"(v.x), "=f"(v.y) : "l"(accA[2*q]));
            asm("mov.b64 {%0, %1}, %2;" : "=f"(v.z), "=f"(v.w) : "l"(accA[2*q+1]));
            g_h[r0 * 16 + q] = v;
            s1 += v.x*aws[4*q] + v.y*aws[4*q+1] + v.z*aws[4*q+2] + v.w*aws[4*q+3];
            s2 += v.x*aws[64+4*q] + v.y*aws[64+4*q+1] + v.z*aws[64+4*q+2] + v.w*aws[64+4*q+3];
        }
        g_s1[n0] = s1; g_s2[n0] = s2;
    }
    if (n1 < NN) {
        float s1 = 0.f, s2 = 0.f;
        #pragma unroll
        for (int q = 0; q < 16; q++) {
            float4 v;
            asm("mov.b64 {%0, %1}, %2;" : "=f"(v.x), "=f"(v.y) : "l"(accB[2*q]));
            asm("mov.b64 {%0, %1}, %2;" : "=f"(v.z), "=f"(v.w) : "l"(accB[2*q+1]));
            g_h[(size_t)n1 * 16 + q] = v;
            s1 += v.x*aws[4*q] + v.y*aws[4*q+1] + v.z*aws[4*q+2] + v.w*aws[4*q+3];
            s2 += v.x*aws[64+4*q] + v.y*aws[64+4*q+1] + v.z*aws[64+4*q+2] + v.w*aws[64+4*q+3];
        }
        g_s1[n1] = s1; g_s2[n1] = s2;
    }
}

// ---------------- K2: fused edge pass ----------------
__global__ void k_edge(const int* __restrict__ eidx) {
    const int t = blockIdx.x * blockDim.x + threadIdx.x;
    const int lane = threadIdx.x & 31;
    const int warp = t >> 5;
    const int nwarps = (gridDim.x * blockDim.x) >> 5;
    const int half = lane >> 4;
    const int l16 = lane & 15;

    float lsum = 0.f;
    for (int e0 = warp * 2; e0 < NE; e0 += nwarps * 2) {
        int e = e0 + half;
        int i = __ldg(eidx + e);
        int j = __ldg(eidx + NE + e);
        float expv = 0.f;
        if (l16 == 0) {
            float l = g_s1[i] + g_s2[j];
            l = (l > 0.f) ? l : 0.2f * l;       // leaky_relu 0.2
            expv = __expf(l);
            lsum += expv;
        }
        expv = __shfl_sync(0xffffffffu, expv, lane & 16);
        float4 hv = g_h[(size_t)j * 16 + l16];
        float* dst = (float*)g_accum + (size_t)i * 64 + l16 * 4;
        asm volatile("red.global.add.v4.f32 [%0], {%1, %2, %3, %4};"
                     :: "l"(dst), "f"(hv.x * expv), "f"(hv.y * expv),
                        "f"(hv.z * expv), "f"(hv.w * expv) : "memory");
    }

    #pragma unroll
    for (int o = 16; o > 0; o >>= 1) lsum += __shfl_down_sync(0xffffffffu, lsum, o);
    __shared__ float wr[8];
    int w = threadIdx.x >> 5;
    if (lane == 0) wr[w] = lsum;
    __syncthreads();
    if (w == 0) {
        float v = (lane < 8) ? wr[lane] : 0.f;
        #pragma unroll
        for (int o = 4; o > 0; o >>= 1) v += __shfl_down_sync(0xffffffffu, v, o);
        if (lane == 0) atomicAdd(&g_sum, v);
    }
}

// ---------------- K3: normalize + tile into 8 heads ----------------
__global__ void k_expand(float* __restrict__ out) {
    int idx = blockIdx.x * blockDim.x + threadIdx.x;
    if (idx >= NN * 16) return;
    float inv = 1.0f / g_sum;
    int n = idx >> 4;
    int c4 = idx & 15;
    float4 v = g_accum[idx];
    v.x *= inv; v.y *= inv; v.z *= inv; v.w *= inv;
    float4* o = (float4*)out + (size_t)n * 128;
    #pragma unroll
    for (int hh = 0; hh < 8; hh++) o[hh * 16 + c4] = v;
}

extern "C" void kernel_launch(void* const* d_in, const int* in_sizes, int n_in,
                              void* d_out, int out_size) {
    const float* x    = (const float*)d_in[0];
    const int*   eidx = (const int*)d_in[1];
    const float* W    = (const float*)d_in[2];
    const float* attn = (const float*)d_in[3];
    float* out = (float*)d_out;

    k_zero<<<(NN * 16 + 255) / 256, 256>>>();
    k_gemm<<<148, 256>>>(x, W, attn);
    k_edge<<<2048, 256>>>(eidx);
    k_expand<<<(NN * 16 + 255) / 256, 256>>>(out);
}